// round 1
// baseline (speedup 1.0000x reference)
#include <cuda_runtime.h>
#include <cstdint>

#define B_   32
#define T_   512
#define E2   512
#define H_   1024
#define G_   4096
#define BT   16384
#define N0   2048
#define N1   512
#define NCTA 128

// ------------------------- scratch (device globals, no allocs) -----------
__device__ float g_x[(size_t)BT * E2];        // packed embeddings [t][b][512]
__device__ float g_xproj[(size_t)BT * G_];    // x @ W_ih^T + b   [t*32+b][4096]
__device__ float g_hs[(size_t)BT * H_];       // h per step       [t][b][1024]
__device__ unsigned g_bar_cnt;
__device__ unsigned g_bar_gen;

// ------------------------- helpers ---------------------------------------
__device__ __forceinline__ uint32_t f2tf(float f) {
    uint32_t u;
    asm("cvt.rna.tf32.f32 %0, %1;" : "=r"(u) : "f"(f));
    return u;
}

__device__ __forceinline__ void mma_tf32(float& c0, float& c1, float& c2, float& c3,
                                         uint32_t a0, uint32_t a1, uint32_t a2, uint32_t a3,
                                         uint32_t b0, uint32_t b1) {
    asm volatile(
        "mma.sync.aligned.m16n8k8.row.col.f32.tf32.tf32.f32 "
        "{%0,%1,%2,%3},{%4,%5,%6,%7},{%8,%9},{%0,%1,%2,%3};"
        : "+f"(c0), "+f"(c1), "+f"(c2), "+f"(c3)
        : "r"(a0), "r"(a1), "r"(a2), "r"(a3), "r"(b0), "r"(b1));
}

__device__ __forceinline__ unsigned ld_acq(const unsigned* p) {
    unsigned v;
    asm volatile("ld.acquire.gpu.u32 %0, [%1];" : "=r"(v) : "l"(p));
    return v;
}

// ------------------------- pack: gather embeddings -----------------------
__global__ void pack_kernel(const int* __restrict__ tok0, const int* __restrict__ tok1,
                            const float* __restrict__ emb0, const float* __restrict__ emb1) {
    int row = blockIdx.x;           // row = t*32 + b
    int t = row >> 5, b = row & 31;
    int tid = threadIdx.x;          // 128 threads, 512 floats per row
    float4* dst = reinterpret_cast<float4*>(g_x + (size_t)row * E2);
    if (tid < 64) {
        int tk = tok0[b * T_ + t];
        dst[tid] = reinterpret_cast<const float4*>(emb0 + (size_t)tk * 256)[tid];
    } else {
        int tk = tok1[b * T_ + t];
        dst[tid] = reinterpret_cast<const float4*>(emb1 + (size_t)tk * 256)[tid - 64];
    }
}

// ------------------------- generic tf32 GEMM ------------------------------
// C[M,N] = A[M,K] @ Bm[N,K]^T + bias1 + bias2.  BM=128, BN=64, BK=32, 256 thr.
// REMAP: output row = (m%32)*512 + m/32   (t*B+b -> b*T+t) for the decoders.
template <bool REMAP>
__launch_bounds__(256, 2)
__global__ void gemm_tf32_kernel(const float* __restrict__ A, const float* __restrict__ Bm,
                                 const float* __restrict__ bias1, const float* __restrict__ bias2,
                                 float* __restrict__ C, int M, int N, int K) {
    extern __shared__ uint32_t smem[];
    uint32_t* sA = smem;                 // [2][128][36]
    uint32_t* sB = smem + 2 * 128 * 36;  // [2][64][36]

    const int tid = threadIdx.x;
    const int bn = blockIdx.x * 64;
    const int bm = blockIdx.y * 128;
    const int lane = tid & 31, warp = tid >> 5;
    const int wm = (warp >> 1) * 32;     // 0,32,64,96
    const int wn = (warp & 1) * 32;      // 0,32
    const int grp = lane >> 2, tig = lane & 3;
    const int KT = K >> 5;

    float4 ra[4], rb[2];

    auto gload = [&](int kb) {
#pragma unroll
        for (int i = 0; i < 4; i++) {
            int lin = tid + i * 256;
            int r = lin >> 3, c4 = lin & 7;
            ra[i] = reinterpret_cast<const float4*>(A + (size_t)(bm + r) * K + kb * 32)[c4];
        }
#pragma unroll
        for (int i = 0; i < 2; i++) {
            int lin = tid + i * 256;
            int r = lin >> 3, c4 = lin & 7;
            rb[i] = reinterpret_cast<const float4*>(Bm + (size_t)(bn + r) * K + kb * 32)[c4];
        }
    };
    auto sstore = [&](int buf) {
        uint32_t* a = sA + buf * 128 * 36;
        uint32_t* b = sB + buf * 64 * 36;
#pragma unroll
        for (int i = 0; i < 4; i++) {
            int lin = tid + i * 256;
            int r = lin >> 3, c4 = lin & 7;
            uint32_t* p = a + r * 36 + c4 * 4;
            p[0] = f2tf(ra[i].x); p[1] = f2tf(ra[i].y);
            p[2] = f2tf(ra[i].z); p[3] = f2tf(ra[i].w);
        }
#pragma unroll
        for (int i = 0; i < 2; i++) {
            int lin = tid + i * 256;
            int r = lin >> 3, c4 = lin & 7;
            uint32_t* p = b + r * 36 + c4 * 4;
            p[0] = f2tf(rb[i].x); p[1] = f2tf(rb[i].y);
            p[2] = f2tf(rb[i].z); p[3] = f2tf(rb[i].w);
        }
    };

    float acc[2][4][4];
#pragma unroll
    for (int i = 0; i < 2; i++)
#pragma unroll
        for (int j = 0; j < 4; j++)
#pragma unroll
            for (int r = 0; r < 4; r++) acc[i][j][r] = 0.f;

    gload(0);
    sstore(0);
    __syncthreads();

    for (int kb = 0; kb < KT; kb++) {
        if (kb + 1 < KT) gload(kb + 1);
        const uint32_t* a_s = sA + (kb & 1) * 128 * 36;
        const uint32_t* b_s = sB + (kb & 1) * 64 * 36;
#pragma unroll
        for (int kt = 0; kt < 4; kt++) {
            int k0 = kt * 8;
            uint32_t af[2][4], bf[4][2];
#pragma unroll
            for (int i = 0; i < 2; i++) {
                int r = wm + i * 16 + grp;
                af[i][0] = a_s[r * 36 + k0 + tig];
                af[i][1] = a_s[(r + 8) * 36 + k0 + tig];
                af[i][2] = a_s[r * 36 + k0 + tig + 4];
                af[i][3] = a_s[(r + 8) * 36 + k0 + tig + 4];
            }
#pragma unroll
            for (int j = 0; j < 4; j++) {
                int n = wn + j * 8 + grp;
                bf[j][0] = b_s[n * 36 + k0 + tig];
                bf[j][1] = b_s[n * 36 + k0 + tig + 4];
            }
#pragma unroll
            for (int i = 0; i < 2; i++)
#pragma unroll
                for (int j = 0; j < 4; j++)
                    mma_tf32(acc[i][j][0], acc[i][j][1], acc[i][j][2], acc[i][j][3],
                             af[i][0], af[i][1], af[i][2], af[i][3], bf[j][0], bf[j][1]);
        }
        if (kb + 1 < KT) {
            __syncthreads();
            sstore((kb + 1) & 1);
            __syncthreads();
        }
    }

    // epilogue
#pragma unroll
    for (int i = 0; i < 2; i++) {
#pragma unroll
        for (int j = 0; j < 4; j++) {
            int col = bn + wn + j * 8 + tig * 2;
            float bv0 = 0.f, bv1 = 0.f;
            if (bias1) { bv0 = bias1[col]; bv1 = bias1[col + 1]; }
            if (bias2) { bv0 += bias2[col]; bv1 += bias2[col + 1]; }
            int r0 = bm + wm + i * 16 + grp;
            int r1 = r0 + 8;
            int or0 = REMAP ? ((r0 & 31) * T_ + (r0 >> 5)) : r0;
            int or1 = REMAP ? ((r1 & 31) * T_ + (r1 >> 5)) : r1;
            float2 v0 = make_float2(acc[i][j][0] + bv0, acc[i][j][1] + bv1);
            float2 v1 = make_float2(acc[i][j][2] + bv0, acc[i][j][3] + bv1);
            *reinterpret_cast<float2*>(C + (size_t)or0 * N + col) = v0;
            *reinterpret_cast<float2*>(C + (size_t)or1 * N + col) = v1;
        }
    }
}

// ------------------------- persistent LSTM recurrence ---------------------
// 128 CTAs x 256 thr. CTA owns 8 hidden units -> 32 gate rows (4 gates x 8).
// W_hh slice cached in SMEM (tf32). Per step: gates = h @ W^T + xproj,
// elementwise LSTM cell, write hs[t], grid barrier.
__launch_bounds__(256, 1)
__global__ void recurrence_kernel(const float* __restrict__ h0, const float* __restrict__ c0,
                                  const float* __restrict__ W_hh, float* __restrict__ d_out) {
    extern __shared__ uint32_t smem[];
    uint32_t* sW = smem;                              // [32][1028] tf32
    uint32_t* sh = sW + 32 * 1028;                    // [32][260]  tf32 (h chunk)
    float* sg = reinterpret_cast<float*>(sh + 32 * 260);  // [4][32][8] gate preacts
    float* sc = sg + 4 * 256;                             // [256] cell state

    const int tid = threadIdx.x;
    const int cta = blockIdx.x;
    const int lane = tid & 31, warp = tid >> 5;
    const int mtile = warp >> 2;      // batch half: 0 or 1
    const int g = warp & 3;           // gate: i,f,g,o
    const int grp = lane >> 2, tig = lane & 3;

    // cache W_hh slice: gate rows g*1024 + cta*8 + r  -> smem row g*8+r
#pragma unroll
    for (int i = 0; i < 32; i++) {
        int lin = tid + i * 256;      // 0..8191 float4
        int r = lin >> 8, c4 = lin & 255;
        int gg = r >> 3, rr = r & 7;
        float4 v = reinterpret_cast<const float4*>(
            W_hh + (size_t)(gg * 1024 + cta * 8 + rr) * 1024)[c4];
        uint32_t* p = sW + r * 1028 + c4 * 4;
        p[0] = f2tf(v.x); p[1] = f2tf(v.y); p[2] = f2tf(v.z); p[3] = f2tf(v.w);
    }
    sc[tid] = c0[(size_t)(tid >> 3) * H_ + cta * 8 + (tid & 7)];

    unsigned gen0 = 0;
    if (tid == 0) gen0 = *(volatile unsigned*)&g_bar_gen;
    __syncthreads();

    const int brow0 = mtile * 16 + grp;
    const int ucol = tig * 2;

    for (int t = 0; t < T_; t++) {
        const float* hsrc = (t == 0) ? h0 : (g_hs + (size_t)(t - 1) * B_ * H_);

        // prefetch xproj contributions (consumed after mma loop)
        const size_t xbase = (size_t)t * B_ * G_ + (size_t)g * H_ + (size_t)cta * 8;
        float xp0a = g_xproj[xbase + (size_t)brow0 * G_ + ucol];
        float xp0b = g_xproj[xbase + (size_t)brow0 * G_ + ucol + 1];
        float xp1a = g_xproj[xbase + (size_t)(brow0 + 8) * G_ + ucol];
        float xp1b = g_xproj[xbase + (size_t)(brow0 + 8) * G_ + ucol + 1];

        float acc[4][4];
#pragma unroll
        for (int p = 0; p < 4; p++)
#pragma unroll
            for (int r = 0; r < 4; r++) acc[p][r] = 0.f;

#pragma unroll 1
        for (int kc = 0; kc < 4; kc++) {
            __syncthreads();
            // stage h chunk [32][256] as tf32
#pragma unroll
            for (int i = 0; i < 8; i++) {
                int lin = tid + i * 256;
                int r = lin >> 6, c4 = lin & 63;
                float4 v = reinterpret_cast<const float4*>(hsrc + (size_t)r * H_ + kc * 256)[c4];
                uint32_t* p = sh + r * 260 + c4 * 4;
                p[0] = f2tf(v.x); p[1] = f2tf(v.y); p[2] = f2tf(v.z); p[3] = f2tf(v.w);
            }
            __syncthreads();

            const uint32_t* arow = sh + (mtile * 16 + grp) * 260;
            const uint32_t* brow = sW + (g * 8 + grp) * 1028 + kc * 256;
#pragma unroll 8
            for (int kk = 0; kk < 32; kk++) {
                int k0 = kk * 8;
                uint32_t a0 = arow[k0 + tig];
                uint32_t a1 = arow[8 * 260 + k0 + tig];
                uint32_t a2 = arow[k0 + tig + 4];
                uint32_t a3 = arow[8 * 260 + k0 + tig + 4];
                uint32_t b0 = brow[k0 + tig];
                uint32_t b1 = brow[k0 + tig + 4];
                float* ac = acc[kk & 3];
                mma_tf32(ac[0], ac[1], ac[2], ac[3], a0, a1, a2, a3, b0, b1);
            }
        }

        float r0 = acc[0][0] + acc[1][0] + acc[2][0] + acc[3][0] + xp0a;
        float r1 = acc[0][1] + acc[1][1] + acc[2][1] + acc[3][1] + xp0b;
        float r2 = acc[0][2] + acc[1][2] + acc[2][2] + acc[3][2] + xp1a;
        float r3 = acc[0][3] + acc[1][3] + acc[2][3] + acc[3][3] + xp1b;

        sg[g * 256 + brow0 * 8 + ucol] = r0;
        sg[g * 256 + brow0 * 8 + ucol + 1] = r1;
        sg[g * 256 + (brow0 + 8) * 8 + ucol] = r2;
        sg[g * 256 + (brow0 + 8) * 8 + ucol + 1] = r3;
        __syncthreads();

        {
            int b = tid >> 3, u = tid & 7;
            float iv = sg[0 * 256 + tid];
            float fv = sg[1 * 256 + tid];
            float gv = sg[2 * 256 + tid];
            float ov = sg[3 * 256 + tid];
            iv = 1.f / (1.f + expf(-iv));
            fv = 1.f / (1.f + expf(-fv));
            gv = tanhf(gv);
            ov = 1.f / (1.f + expf(-ov));
            float c = fv * sc[tid] + iv * gv;
            sc[tid] = c;
            float h = ov * tanhf(c);
            g_hs[(size_t)t * B_ * H_ + (size_t)b * H_ + cta * 8 + u] = h;
            if (t == T_ - 1) {
                size_t off_h = (size_t)B_ * T_ * (N0 + N1);
                d_out[off_h + (size_t)b * H_ + cta * 8 + u] = h;
                d_out[off_h + (size_t)B_ * H_ + (size_t)b * H_ + cta * 8 + u] = c;
            }
        }

        if (t < T_ - 1) {
            __threadfence();
            __syncthreads();
            if (tid == 0) {
                unsigned arrive = atomicAdd(&g_bar_cnt, 1);
                if (arrive == NCTA - 1) {
                    atomicExch(&g_bar_cnt, 0);
                    __threadfence();
                    atomicAdd(&g_bar_gen, 1);
                } else {
                    while (ld_acq(&g_bar_gen) - gen0 < (unsigned)(t + 1)) {}
                }
            }
            __syncthreads();
        }
    }
}

// ------------------------- launch ----------------------------------------
extern "C" void kernel_launch(void* const* d_in, const int* in_sizes, int n_in,
                              void* d_out, int out_size) {
    const int*   tok0 = (const int*)d_in[0];
    const int*   tok1 = (const int*)d_in[1];
    const float* h0   = (const float*)d_in[2];
    const float* c0   = (const float*)d_in[3];
    const float* emb0 = (const float*)d_in[4];
    const float* emb1 = (const float*)d_in[5];
    const float* W_ih = (const float*)d_in[6];
    const float* W_hh = (const float*)d_in[7];
    const float* b_ih = (const float*)d_in[8];
    const float* b_hh = (const float*)d_in[9];
    const float* Wd0  = (const float*)d_in[10];
    const float* bd0  = (const float*)d_in[11];
    const float* Wd1  = (const float*)d_in[12];
    const float* bd1  = (const float*)d_in[13];
    float* out = (float*)d_out;

    const int GEMM_SMEM = (2 * 128 * 36 + 2 * 64 * 36) * 4;                       // 55296
    const int REC_SMEM  = (32 * 1028 + 32 * 260 + 4 * 256 + 256) * 4;             // 169984

    cudaFuncSetAttribute(gemm_tf32_kernel<false>, cudaFuncAttributeMaxDynamicSharedMemorySize, GEMM_SMEM);
    cudaFuncSetAttribute(gemm_tf32_kernel<true>,  cudaFuncAttributeMaxDynamicSharedMemorySize, GEMM_SMEM);
    cudaFuncSetAttribute(recurrence_kernel, cudaFuncAttributeMaxDynamicSharedMemorySize, REC_SMEM);

    void *px, *pxp, *phs;
    cudaGetSymbolAddress(&px, g_x);
    cudaGetSymbolAddress(&pxp, g_xproj);
    cudaGetSymbolAddress(&phs, g_hs);

    pack_kernel<<<BT, 128>>>(tok0, tok1, emb0, emb1);

    // xproj = x @ W_ih^T + (b_ih + b_hh)
    gemm_tf32_kernel<false><<<dim3(G_ / 64, BT / 128), 256, GEMM_SMEM>>>(
        (const float*)px, W_ih, b_ih, b_hh, (float*)pxp, BT, G_, E2);

    recurrence_kernel<<<NCTA, 256, REC_SMEM>>>(h0, c0, W_hh, out);

    // dec0 = hs @ Wd0^T + bd0   (rows remapped t*B+b -> b*T+t)
    gemm_tf32_kernel<true><<<dim3(N0 / 64, BT / 128), 256, GEMM_SMEM>>>(
        (const float*)phs, Wd0, bd0, nullptr, out, BT, N0, H_);

    // dec1 = hs @ Wd1^T + bd1
    gemm_tf32_kernel<true><<<dim3(N1 / 64, BT / 128), 256, GEMM_SMEM>>>(
        (const float*)phs, Wd1, bd1, nullptr, out + (size_t)BT * N0, BT, N1, H_);
}

// round 2
// speedup vs baseline: 1.2174x; 1.2174x over previous
#include <cuda_runtime.h>
#include <cstdint>

#define B_   32
#define T_   512
#define E2   512
#define H_   1024
#define G_   4096
#define BT   16384
#define N0   2048
#define N1   512
#define NCTA 128

// ------------------------- scratch (device globals, no allocs) -----------
__device__ float g_x[(size_t)BT * E2];        // packed embeddings [t][b][512]
__device__ float g_xproj[(size_t)BT * G_];    // x @ W_ih^T + b   [t*32+b][4096]
__device__ float g_hs[(size_t)BT * H_];       // h per step fp32  [t*32+b][1024]
__device__ uint32_t g_htf[2][B_ * H_];        // h as tf32 bits, double buffered
__device__ uint32_t g_whh_tf[(size_t)G_ * H_]; // W_hh pre-converted to tf32
__device__ unsigned g_bar_cnt;
__device__ unsigned g_bar_gen;

// ------------------------- helpers ---------------------------------------
__device__ __forceinline__ uint32_t f2tf(float f) {
    uint32_t u;
    asm("cvt.rna.tf32.f32 %0, %1;" : "=r"(u) : "f"(f));
    return u;
}

__device__ __forceinline__ void mma_tf32(float& c0, float& c1, float& c2, float& c3,
                                         uint32_t a0, uint32_t a1, uint32_t a2, uint32_t a3,
                                         uint32_t b0, uint32_t b1) {
    asm volatile(
        "mma.sync.aligned.m16n8k8.row.col.f32.tf32.tf32.f32 "
        "{%0,%1,%2,%3},{%4,%5,%6,%7},{%8,%9},{%0,%1,%2,%3};"
        : "+f"(c0), "+f"(c1), "+f"(c2), "+f"(c3)
        : "r"(a0), "r"(a1), "r"(a2), "r"(a3), "r"(b0), "r"(b1));
}

__device__ __forceinline__ void ldsm4(uint32_t& r0, uint32_t& r1, uint32_t& r2, uint32_t& r3,
                                      uint32_t saddr) {
    asm volatile("ldmatrix.sync.aligned.m8n8.x4.shared.b16 {%0,%1,%2,%3}, [%4];"
                 : "=r"(r0), "=r"(r1), "=r"(r2), "=r"(r3) : "r"(saddr));
}

__device__ __forceinline__ void cp16(uint32_t sdst, const void* gsrc) {
    asm volatile("cp.async.cg.shared.global [%0], [%1], 16;" :: "r"(sdst), "l"(gsrc) : "memory");
}

__device__ __forceinline__ unsigned ld_acq(const unsigned* p) {
    unsigned v;
    asm volatile("ld.acquire.gpu.u32 %0, [%1];" : "=r"(v) : "l"(p));
    return v;
}

// ------------------------- prep: convert weights / h0 to tf32 ------------
__global__ void prep_kernel(const float* __restrict__ W_hh, const float* __restrict__ h0) {
    size_t i = (size_t)blockIdx.x * blockDim.x + threadIdx.x;
    size_t stride = (size_t)gridDim.x * blockDim.x;
    const size_t n = (size_t)G_ * H_;
    for (size_t k = i; k < n; k += stride) g_whh_tf[k] = f2tf(W_hh[k]);
    if (i < (size_t)B_ * H_) g_htf[1][i] = f2tf(h0[i]);   // h[-1] lives in buffer 1
}

// ------------------------- pack: gather embeddings -----------------------
__global__ void pack_kernel(const int* __restrict__ tok0, const int* __restrict__ tok1,
                            const float* __restrict__ emb0, const float* __restrict__ emb1) {
    int row = blockIdx.x;           // row = t*32 + b
    int t = row >> 5, b = row & 31;
    int tid = threadIdx.x;          // 128 threads, 512 floats per row
    float4* dst = reinterpret_cast<float4*>(g_x + (size_t)row * E2);
    if (tid < 64) {
        int tk = tok0[b * T_ + t];
        dst[tid] = reinterpret_cast<const float4*>(emb0 + (size_t)tk * 256)[tid];
    } else {
        int tk = tok1[b * T_ + t];
        dst[tid] = reinterpret_cast<const float4*>(emb1 + (size_t)tk * 256)[tid - 64];
    }
}

// ------------------------- generic tf32 GEMM (unchanged, known-good) -----
template <bool REMAP>
__launch_bounds__(256, 2)
__global__ void gemm_tf32_kernel(const float* __restrict__ A, const float* __restrict__ Bm,
                                 const float* __restrict__ bias1, const float* __restrict__ bias2,
                                 float* __restrict__ C, int M, int N, int K) {
    extern __shared__ uint32_t smem[];
    uint32_t* sA = smem;                 // [2][128][36]
    uint32_t* sB = smem + 2 * 128 * 36;  // [2][64][36]

    const int tid = threadIdx.x;
    const int bn = blockIdx.x * 64;
    const int bm = blockIdx.y * 128;
    const int lane = tid & 31, warp = tid >> 5;
    const int wm = (warp >> 1) * 32;
    const int wn = (warp & 1) * 32;
    const int grp = lane >> 2, tig = lane & 3;
    const int KT = K >> 5;

    float4 ra[4], rb[2];

    auto gload = [&](int kb) {
#pragma unroll
        for (int i = 0; i < 4; i++) {
            int lin = tid + i * 256;
            int r = lin >> 3, c4 = lin & 7;
            ra[i] = reinterpret_cast<const float4*>(A + (size_t)(bm + r) * K + kb * 32)[c4];
        }
#pragma unroll
        for (int i = 0; i < 2; i++) {
            int lin = tid + i * 256;
            int r = lin >> 3, c4 = lin & 7;
            rb[i] = reinterpret_cast<const float4*>(Bm + (size_t)(bn + r) * K + kb * 32)[c4];
        }
    };
    auto sstore = [&](int buf) {
        uint32_t* a = sA + buf * 128 * 36;
        uint32_t* b = sB + buf * 64 * 36;
#pragma unroll
        for (int i = 0; i < 4; i++) {
            int lin = tid + i * 256;
            int r = lin >> 3, c4 = lin & 7;
            uint32_t* p = a + r * 36 + c4 * 4;
            p[0] = f2tf(ra[i].x); p[1] = f2tf(ra[i].y);
            p[2] = f2tf(ra[i].z); p[3] = f2tf(ra[i].w);
        }
#pragma unroll
        for (int i = 0; i < 2; i++) {
            int lin = tid + i * 256;
            int r = lin >> 3, c4 = lin & 7;
            uint32_t* p = b + r * 36 + c4 * 4;
            p[0] = f2tf(rb[i].x); p[1] = f2tf(rb[i].y);
            p[2] = f2tf(rb[i].z); p[3] = f2tf(rb[i].w);
        }
    };

    float acc[2][4][4];
#pragma unroll
    for (int i = 0; i < 2; i++)
#pragma unroll
        for (int j = 0; j < 4; j++)
#pragma unroll
            for (int r = 0; r < 4; r++) acc[i][j][r] = 0.f;

    gload(0);
    sstore(0);
    __syncthreads();

    for (int kb = 0; kb < KT; kb++) {
        if (kb + 1 < KT) gload(kb + 1);
        const uint32_t* a_s = sA + (kb & 1) * 128 * 36;
        const uint32_t* b_s = sB + (kb & 1) * 64 * 36;
#pragma unroll
        for (int kt = 0; kt < 4; kt++) {
            int k0 = kt * 8;
            uint32_t af[2][4], bf[4][2];
#pragma unroll
            for (int i = 0; i < 2; i++) {
                int r = wm + i * 16 + grp;
                af[i][0] = a_s[r * 36 + k0 + tig];
                af[i][1] = a_s[(r + 8) * 36 + k0 + tig];
                af[i][2] = a_s[r * 36 + k0 + tig + 4];
                af[i][3] = a_s[(r + 8) * 36 + k0 + tig + 4];
            }
#pragma unroll
            for (int j = 0; j < 4; j++) {
                int n = wn + j * 8 + grp;
                bf[j][0] = b_s[n * 36 + k0 + tig];
                bf[j][1] = b_s[n * 36 + k0 + tig + 4];
            }
#pragma unroll
            for (int i = 0; i < 2; i++)
#pragma unroll
                for (int j = 0; j < 4; j++)
                    mma_tf32(acc[i][j][0], acc[i][j][1], acc[i][j][2], acc[i][j][3],
                             af[i][0], af[i][1], af[i][2], af[i][3], bf[j][0], bf[j][1]);
        }
        if (kb + 1 < KT) {
            __syncthreads();
            sstore((kb + 1) & 1);
            __syncthreads();
        }
    }

#pragma unroll
    for (int i = 0; i < 2; i++) {
#pragma unroll
        for (int j = 0; j < 4; j++) {
            int col = bn + wn + j * 8 + tig * 2;
            float bv0 = 0.f, bv1 = 0.f;
            if (bias1) { bv0 = bias1[col]; bv1 = bias1[col + 1]; }
            if (bias2) { bv0 += bias2[col]; bv1 += bias2[col + 1]; }
            int r0 = bm + wm + i * 16 + grp;
            int r1 = r0 + 8;
            int or0 = REMAP ? ((r0 & 31) * T_ + (r0 >> 5)) : r0;
            int or1 = REMAP ? ((r1 & 31) * T_ + (r1 >> 5)) : r1;
            float2 v0 = make_float2(acc[i][j][0] + bv0, acc[i][j][1] + bv1);
            float2 v1 = make_float2(acc[i][j][2] + bv0, acc[i][j][3] + bv1);
            *reinterpret_cast<float2*>(C + (size_t)or0 * N + col) = v0;
            *reinterpret_cast<float2*>(C + (size_t)or1 * N + col) = v1;
        }
    }
}

// ------------------------- persistent LSTM recurrence v2 ------------------
// 128 CTAs x 256 thr (8 warps). CTA owns 8 hidden units -> 32 gate rows.
// Warp k-split: warp w computes m32 x n32 over k in [128w, 128w+128),
// partials reduced through smem. h staged via cp.async.cg (tf32 bits, no cvt),
// fragments via ldmatrix.x4 (b16 tiles == 8x4-tf32 fragments).
#define SW_STRIDE 1028
#define SW_WORDS  (32 * SW_STRIDE)          // 32896
#define SA_STRIDE 36
#define SA_BUF_W  (32 * SA_STRIDE)          // 1152
#define SA_WARP_W (2 * SA_BUF_W)            // 2304
#define SA_WORDS  (8 * SA_WARP_W)           // 18432
#define SRED_WRP  (32 * 34)                 // 1088 (overlaid on sA)
#define REC_SMEM_BYTES ((SW_WORDS + SA_WORDS + 256) * 4)

__device__ __forceinline__ void stage_chunk(const uint32_t* __restrict__ hsrc, int kbase,
                                            uint32_t sdst_bytes, int lane) {
#pragma unroll
    for (int j = 0; j < 8; j++) {
        int id = j * 32 + lane;
        int srow = id >> 3;            // 0..31
        int s16 = id & 7;              // 16B column within 32-word chunk
        cp16(sdst_bytes + (uint32_t)(srow * SA_STRIDE + s16 * 4) * 4,
             hsrc + (size_t)srow * H_ + kbase + s16 * 4);
    }
    asm volatile("cp.async.commit_group;" ::: "memory");
}

__launch_bounds__(256, 1)
__global__ void recurrence_kernel(const float* __restrict__ c0, float* __restrict__ d_out) {
    extern __shared__ uint32_t smem[];
    uint32_t* sW = smem;                                   // [32][1028] tf32
    float* sred = reinterpret_cast<float*>(smem + SW_WORDS);   // overlay on sA
    float* sc = reinterpret_cast<float*>(smem + SW_WORDS + SA_WORDS);  // [256]

    const int tid = threadIdx.x;
    const int cta = blockIdx.x;
    const int lane = tid & 31, warp = tid >> 5;
    const uint32_t smem_b = (uint32_t)__cvta_generic_to_shared(smem);
    const int b = tid >> 3, u = tid & 7;

    // --- init: copy pre-converted W_hh slice into sW (pure bit copy) ---
#pragma unroll
    for (int it = 0; it < 32; it++) {
        int lin = tid + it * 256;      // float4 id 0..8191
        int r = lin >> 8;              // smem row 0..31 (g*8+u)
        int c4 = lin & 255;
        int gg = r >> 3, rr = r & 7;
        cp16(smem_b + (uint32_t)(r * SW_STRIDE + c4 * 4) * 4,
             g_whh_tf + (size_t)(gg * H_ + cta * 8 + rr) * H_ + c4 * 4);
    }
    asm volatile("cp.async.commit_group;" ::: "memory");
    sc[tid] = c0[(size_t)b * H_ + cta * 8 + u];
    asm volatile("cp.async.wait_group 0;" ::: "memory");

    unsigned gen0 = 0;
    if (tid == 0) gen0 = *(volatile unsigned*)&g_bar_gen;
    __syncthreads();

    const int kw0 = warp * 128;
    const uint32_t sa_bytes = smem_b + (uint32_t)(SW_WORDS + warp * SA_WARP_W) * 4;

    for (int t = 0; t < T_; t++) {
        const uint32_t* hsrc = g_htf[(t + 1) & 1];   // h[t-1]

        // prefetch xproj (consumed in epilogue)
        const size_t xb = (size_t)(t * B_ + b) * G_ + (size_t)cta * 8 + u;
        float xp0 = g_xproj[xb];
        float xp1 = g_xproj[xb + H_];
        float xp2 = g_xproj[xb + 2 * H_];
        float xp3 = g_xproj[xb + 3 * H_];

        float acc[2][4][4];
#pragma unroll
        for (int i = 0; i < 2; i++)
#pragma unroll
            for (int j = 0; j < 4; j++)
#pragma unroll
                for (int r = 0; r < 4; r++) acc[i][j][r] = 0.f;

        stage_chunk(hsrc, kw0, sa_bytes, lane);

#pragma unroll
        for (int cc = 0; cc < 4; cc++) {
            if (cc < 3) {
                stage_chunk(hsrc, kw0 + (cc + 1) * 32,
                            sa_bytes + (uint32_t)(((cc + 1) & 1) * SA_BUF_W) * 4, lane);
                asm volatile("cp.async.wait_group 1;" ::: "memory");
            } else {
                asm volatile("cp.async.wait_group 0;" ::: "memory");
            }
            __syncwarp();

            const uint32_t abase = sa_bytes + (uint32_t)((cc & 1) * SA_BUF_W) * 4;
            const int colc = kw0 + cc * 32;
            const int arow = ((lane >> 3) & 1) * 8 + (lane & 7);
            const int ahi = (lane >> 4) * 4;

#pragma unroll
            for (int kp = 0; kp < 2; kp++) {
                uint32_t bfr[4][4];
#pragma unroll
                for (int j = 0; j < 4; j++) {
                    int n = j * 8 + (lane & 7);
                    int col = colc + kp * 16 + (lane >> 3) * 4;
                    ldsm4(bfr[j][0], bfr[j][1], bfr[j][2], bfr[j][3],
                          smem_b + (uint32_t)(n * SW_STRIDE + col) * 4);
                }
#pragma unroll
                for (int k2 = 0; k2 < 2; k2++) {
                    int kt = kp * 2 + k2;
                    uint32_t afr[2][4];
#pragma unroll
                    for (int i = 0; i < 2; i++) {
                        int row = i * 16 + arow;
                        ldsm4(afr[i][0], afr[i][1], afr[i][2], afr[i][3],
                              abase + (uint32_t)(row * SA_STRIDE + kt * 8 + ahi) * 4);
                    }
#pragma unroll
                    for (int i = 0; i < 2; i++)
#pragma unroll
                        for (int j = 0; j < 4; j++)
                            mma_tf32(acc[i][j][0], acc[i][j][1], acc[i][j][2], acc[i][j][3],
                                     afr[i][0], afr[i][1], afr[i][2], afr[i][3],
                                     bfr[j][k2 * 2], bfr[j][k2 * 2 + 1]);
                }
            }
        }

        __syncthreads();   // all warps done with sA -> safe to overlay sred

        // write k-partials: warp w -> sred[w][m 32][n 32] (pad 34)
        const int grp = lane >> 2, tig = lane & 3;
#pragma unroll
        for (int i = 0; i < 2; i++) {
#pragma unroll
            for (int j = 0; j < 4; j++) {
                int m0 = i * 16 + grp, n0 = j * 8 + tig * 2;
                float* p = sred + warp * SRED_WRP;
                *reinterpret_cast<float2*>(p + m0 * 34 + n0) =
                    make_float2(acc[i][j][0], acc[i][j][1]);
                *reinterpret_cast<float2*>(p + (m0 + 8) * 34 + n0) =
                    make_float2(acc[i][j][2], acc[i][j][3]);
            }
        }
        __syncthreads();

        // reduce 8 partials + xproj, LSTM cell
        float s0 = xp0, s1 = xp1, s2 = xp2, s3 = xp3;
#pragma unroll
        for (int w = 0; w < 8; w++) {
            const float* p = sred + w * SRED_WRP + b * 34 + u;
            s0 += p[0]; s1 += p[8]; s2 += p[16]; s3 += p[24];
        }
        float iv = 1.f / (1.f + expf(-s0));
        float fv = 1.f / (1.f + expf(-s1));
        float gv = tanhf(s2);
        float ov = 1.f / (1.f + expf(-s3));
        float c = fv * sc[tid] + iv * gv;
        sc[tid] = c;
        float h = ov * tanhf(c);

        g_hs[(size_t)(t * B_ + b) * H_ + cta * 8 + u] = h;
        g_htf[t & 1][b * H_ + cta * 8 + u] = f2tf(h);
        if (t == T_ - 1) {
            size_t off_h = (size_t)BT * (N0 + N1);
            d_out[off_h + (size_t)b * H_ + cta * 8 + u] = h;
            d_out[off_h + (size_t)B_ * H_ + (size_t)b * H_ + cta * 8 + u] = c;
        }

        if (t < T_ - 1) {
            __threadfence();
            __syncthreads();
            if (tid == 0) {
                unsigned arrive = atomicAdd(&g_bar_cnt, 1);
                if (arrive == NCTA - 1) {
                    atomicExch(&g_bar_cnt, 0);
                    __threadfence();
                    atomicAdd(&g_bar_gen, 1);
                } else {
                    while (ld_acq(&g_bar_gen) - gen0 < (unsigned)(t + 1)) {}
                }
            }
            __syncthreads();
        }
    }
}

// ------------------------- launch ----------------------------------------
extern "C" void kernel_launch(void* const* d_in, const int* in_sizes, int n_in,
                              void* d_out, int out_size) {
    const int*   tok0 = (const int*)d_in[0];
    const int*   tok1 = (const int*)d_in[1];
    const float* h0   = (const float*)d_in[2];
    const float* c0   = (const float*)d_in[3];
    const float* emb0 = (const float*)d_in[4];
    const float* emb1 = (const float*)d_in[5];
    const float* W_ih = (const float*)d_in[6];
    const float* W_hh = (const float*)d_in[7];
    const float* b_ih = (const float*)d_in[8];
    const float* b_hh = (const float*)d_in[9];
    const float* Wd0  = (const float*)d_in[10];
    const float* bd0  = (const float*)d_in[11];
    const float* Wd1  = (const float*)d_in[12];
    const float* bd1  = (const float*)d_in[13];
    float* out = (float*)d_out;

    const int GEMM_SMEM = (2 * 128 * 36 + 2 * 64 * 36) * 4;   // 55296

    cudaFuncSetAttribute(gemm_tf32_kernel<false>, cudaFuncAttributeMaxDynamicSharedMemorySize, GEMM_SMEM);
    cudaFuncSetAttribute(gemm_tf32_kernel<true>,  cudaFuncAttributeMaxDynamicSharedMemorySize, GEMM_SMEM);
    cudaFuncSetAttribute(recurrence_kernel, cudaFuncAttributeMaxDynamicSharedMemorySize, REC_SMEM_BYTES);

    void *px, *pxp, *phs;
    cudaGetSymbolAddress(&px, g_x);
    cudaGetSymbolAddress(&pxp, g_xproj);
    cudaGetSymbolAddress(&phs, g_hs);

    prep_kernel<<<4096, 256>>>(W_hh, h0);
    pack_kernel<<<BT, 128>>>(tok0, tok1, emb0, emb1);

    // xproj = x @ W_ih^T + (b_ih + b_hh)
    gemm_tf32_kernel<false><<<dim3(G_ / 64, BT / 128), 256, GEMM_SMEM>>>(
        (const float*)px, W_ih, b_ih, b_hh, (float*)pxp, BT, G_, E2);

    recurrence_kernel<<<NCTA, 256, REC_SMEM_BYTES>>>(c0, out);

    // dec0 = hs @ Wd0^T + bd0   (rows remapped t*B+b -> b*T+t)
    gemm_tf32_kernel<true><<<dim3(N0 / 64, BT / 128), 256, GEMM_SMEM>>>(
        (const float*)phs, Wd0, bd0, nullptr, out, BT, N0, H_);

    // dec1 = hs @ Wd1^T + bd1
    gemm_tf32_kernel<true><<<dim3(N1 / 64, BT / 128), 256, GEMM_SMEM>>>(
        (const float*)phs, Wd1, bd1, nullptr, out + (size_t)BT * N0, BT, N1, H_);
}

// round 3
// speedup vs baseline: 1.3324x; 1.0944x over previous
#include <cuda_runtime.h>
#include <cstdint>

#define B_   32
#define T_   512
#define E2   512
#define H_   1024
#define G_   4096
#define BT   16384
#define N0   2048
#define N1   512
#define NCTA 128

// ------------------------- scratch (device globals, no allocs) -----------
__device__ uint32_t g_x[(size_t)BT * E2];          // embeddings, tf32 bits
__device__ float    g_xproj[(size_t)BT * G_];      // x @ W_ih^T + b (fp32)
__device__ uint32_t g_hstf[(size_t)(BT + B_) * H_];// tf32 h: rows 0..31 = h0, row (t+1)*32+b = h[t]
__device__ uint32_t g_wih_tf[(size_t)G_ * E2];
__device__ uint32_t g_whh_tf[(size_t)G_ * H_];
__device__ uint32_t g_wd0_tf[(size_t)N0 * H_];
__device__ uint32_t g_wd1_tf[(size_t)N1 * H_];
__device__ unsigned g_gcnt[8];                     // per-group step counters

// ------------------------- helpers ---------------------------------------
__device__ __forceinline__ uint32_t f2tf(float f) {
    uint32_t u;
    asm("cvt.rna.tf32.f32 %0, %1;" : "=r"(u) : "f"(f));
    return u;
}

__device__ __forceinline__ void mma_tf32(float& c0, float& c1, float& c2, float& c3,
                                         uint32_t a0, uint32_t a1, uint32_t a2, uint32_t a3,
                                         uint32_t b0, uint32_t b1) {
    asm volatile(
        "mma.sync.aligned.m16n8k8.row.col.f32.tf32.tf32.f32 "
        "{%0,%1,%2,%3},{%4,%5,%6,%7},{%8,%9},{%0,%1,%2,%3};"
        : "+f"(c0), "+f"(c1), "+f"(c2), "+f"(c3)
        : "r"(a0), "r"(a1), "r"(a2), "r"(a3), "r"(b0), "r"(b1));
}

__device__ __forceinline__ void ldsm4(uint32_t& r0, uint32_t& r1, uint32_t& r2, uint32_t& r3,
                                      uint32_t saddr) {
    asm volatile("ldmatrix.sync.aligned.m8n8.x4.shared.b16 {%0,%1,%2,%3}, [%4];"
                 : "=r"(r0), "=r"(r1), "=r"(r2), "=r"(r3) : "r"(saddr));
}

__device__ __forceinline__ void cp16(uint32_t sdst, const void* gsrc) {
    asm volatile("cp.async.cg.shared.global [%0], [%1], 16;" :: "r"(sdst), "l"(gsrc) : "memory");
}

__device__ __forceinline__ unsigned ld_acq(const unsigned* p) {
    unsigned v;
    asm volatile("ld.acquire.gpu.u32 %0, [%1];" : "=r"(v) : "l"(p));
    return v;
}

__device__ __forceinline__ void red_release(unsigned* p, unsigned v) {
    asm volatile("red.release.gpu.global.add.u32 [%0], %1;" :: "l"(p), "r"(v) : "memory");
}

// ------------------------- prep: convert weights / h0, reset counters ----
__global__ void prep_kernel(const float* __restrict__ W_ih, const float* __restrict__ W_hh,
                            const float* __restrict__ Wd0, const float* __restrict__ Wd1,
                            const float* __restrict__ h0) {
    size_t i = (size_t)blockIdx.x * blockDim.x + threadIdx.x;
    size_t stride = (size_t)gridDim.x * blockDim.x;
    for (size_t k = i; k < (size_t)G_ * H_; k += stride) g_whh_tf[k] = f2tf(W_hh[k]);
    for (size_t k = i; k < (size_t)G_ * E2; k += stride) g_wih_tf[k] = f2tf(W_ih[k]);
    for (size_t k = i; k < (size_t)N0 * H_; k += stride) g_wd0_tf[k] = f2tf(Wd0[k]);
    for (size_t k = i; k < (size_t)N1 * H_; k += stride) g_wd1_tf[k] = f2tf(Wd1[k]);
    if (i < (size_t)B_ * H_) g_hstf[i] = f2tf(h0[i]);   // rows 0..31 = h[-1]
    if (i < 8) g_gcnt[i] = 0;
}

// ------------------------- pack: gather embeddings as tf32 ---------------
__global__ void pack_kernel(const int* __restrict__ tok0, const int* __restrict__ tok1,
                            const float* __restrict__ emb0, const float* __restrict__ emb1) {
    int row = blockIdx.x;           // row = t*32 + b
    int t = row >> 5, b = row & 31;
    int tid = threadIdx.x;          // 128 threads, 512 words per row
    uint4* dst = reinterpret_cast<uint4*>(g_x + (size_t)row * E2);
    float4 v;
    if (tid < 64) {
        int tk = tok0[b * T_ + t];
        v = reinterpret_cast<const float4*>(emb0 + (size_t)tk * 256)[tid];
    } else {
        int tk = tok1[b * T_ + t];
        v = reinterpret_cast<const float4*>(emb1 + (size_t)tk * 256)[tid - 64];
    }
    uint4 u = make_uint4(f2tf(v.x), f2tf(v.y), f2tf(v.z), f2tf(v.w));
    dst[tid < 64 ? tid : tid] = u;
}

// ------------------------- generic tf32 GEMM (inputs pre-converted) ------
// C[M,N] = A[M,K] @ Bm[N,K]^T + bias1 + bias2.  BM=128, BN=64, BK=32, 256 thr.
// A, Bm hold tf32 bit patterns. REMAP: out row (m%32)*512 + m/32.
template <bool REMAP>
__launch_bounds__(256, 2)
__global__ void gemm_tf32_kernel(const uint32_t* __restrict__ A, const uint32_t* __restrict__ Bm,
                                 const float* __restrict__ bias1, const float* __restrict__ bias2,
                                 float* __restrict__ C, int M, int N, int K) {
    extern __shared__ uint32_t smem[];
    uint32_t* sA = smem;                 // [2][128][36]
    uint32_t* sB = smem + 2 * 128 * 36;  // [2][64][36]

    const int tid = threadIdx.x;
    const int bn = blockIdx.x * 64;
    const int bm = blockIdx.y * 128;
    const int lane = tid & 31, warp = tid >> 5;
    const int wm = (warp >> 1) * 32;
    const int wn = (warp & 1) * 32;
    const int grp = lane >> 2, tig = lane & 3;
    const int KT = K >> 5;

    uint4 ra[4], rb[2];

    auto gload = [&](int kb) {
#pragma unroll
        for (int i = 0; i < 4; i++) {
            int lin = tid + i * 256;
            int r = lin >> 3, c4 = lin & 7;
            ra[i] = reinterpret_cast<const uint4*>(A + (size_t)(bm + r) * K + kb * 32)[c4];
        }
#pragma unroll
        for (int i = 0; i < 2; i++) {
            int lin = tid + i * 256;
            int r = lin >> 3, c4 = lin & 7;
            rb[i] = reinterpret_cast<const uint4*>(Bm + (size_t)(bn + r) * K + kb * 32)[c4];
        }
    };
    auto sstore = [&](int buf) {
        uint32_t* a = sA + buf * 128 * 36;
        uint32_t* b = sB + buf * 64 * 36;
#pragma unroll
        for (int i = 0; i < 4; i++) {
            int lin = tid + i * 256;
            int r = lin >> 3, c4 = lin & 7;
            *reinterpret_cast<uint4*>(a + r * 36 + c4 * 4) = ra[i];
        }
#pragma unroll
        for (int i = 0; i < 2; i++) {
            int lin = tid + i * 256;
            int r = lin >> 3, c4 = lin & 7;
            *reinterpret_cast<uint4*>(b + r * 36 + c4 * 4) = rb[i];
        }
    };

    float acc[2][4][4];
#pragma unroll
    for (int i = 0; i < 2; i++)
#pragma unroll
        for (int j = 0; j < 4; j++)
#pragma unroll
            for (int r = 0; r < 4; r++) acc[i][j][r] = 0.f;

    gload(0);
    sstore(0);
    __syncthreads();

    for (int kb = 0; kb < KT; kb++) {
        if (kb + 1 < KT) gload(kb + 1);
        const uint32_t* a_s = sA + (kb & 1) * 128 * 36;
        const uint32_t* b_s = sB + (kb & 1) * 64 * 36;
#pragma unroll
        for (int kt = 0; kt < 4; kt++) {
            int k0 = kt * 8;
            uint32_t af[2][4], bf[4][2];
#pragma unroll
            for (int i = 0; i < 2; i++) {
                int r = wm + i * 16 + grp;
                af[i][0] = a_s[r * 36 + k0 + tig];
                af[i][1] = a_s[(r + 8) * 36 + k0 + tig];
                af[i][2] = a_s[r * 36 + k0 + tig + 4];
                af[i][3] = a_s[(r + 8) * 36 + k0 + tig + 4];
            }
#pragma unroll
            for (int j = 0; j < 4; j++) {
                int n = wn + j * 8 + grp;
                bf[j][0] = b_s[n * 36 + k0 + tig];
                bf[j][1] = b_s[n * 36 + k0 + tig + 4];
            }
#pragma unroll
            for (int i = 0; i < 2; i++)
#pragma unroll
                for (int j = 0; j < 4; j++)
                    mma_tf32(acc[i][j][0], acc[i][j][1], acc[i][j][2], acc[i][j][3],
                             af[i][0], af[i][1], af[i][2], af[i][3], bf[j][0], bf[j][1]);
        }
        if (kb + 1 < KT) {
            __syncthreads();
            sstore((kb + 1) & 1);
            __syncthreads();
        }
    }

#pragma unroll
    for (int i = 0; i < 2; i++) {
#pragma unroll
        for (int j = 0; j < 4; j++) {
            int col = bn + wn + j * 8 + tig * 2;
            float bv0 = 0.f, bv1 = 0.f;
            if (bias1) { bv0 = bias1[col]; bv1 = bias1[col + 1]; }
            if (bias2) { bv0 += bias2[col]; bv1 += bias2[col + 1]; }
            int r0 = bm + wm + i * 16 + grp;
            int r1 = r0 + 8;
            int or0 = REMAP ? ((r0 & 31) * T_ + (r0 >> 5)) : r0;
            int or1 = REMAP ? ((r1 & 31) * T_ + (r1 >> 5)) : r1;
            float2 v0 = make_float2(acc[i][j][0] + bv0, acc[i][j][1] + bv1);
            float2 v1 = make_float2(acc[i][j][2] + bv0, acc[i][j][3] + bv1);
            *reinterpret_cast<float2*>(C + (size_t)or0 * N + col) = v0;
            *reinterpret_cast<float2*>(C + (size_t)or1 * N + col) = v1;
        }
    }
}

// ------------------------- persistent LSTM recurrence v3 ------------------
// 128 CTAs x 256 thr (8 warps). CTA owns 8 hidden units -> 32 gate rows.
// Warp w handles k in [128w,128w+128) -> needs h units from CTAs 16w..16w+15
// only. Fine-grained sync: 8 group counters; producer CTA red.release +1 to
// its group's counter after writing h[t]; consumer warp w spins until
// gcnt[w] >= 16*t before staging h[t-1]. No global barrier, no threadfence.
#define SW_STRIDE 1028
#define SW_WORDS  (32 * SW_STRIDE)          // 32896
#define SA_STRIDE 36
#define SA_BUF_W  (32 * SA_STRIDE)          // 1152
#define SA_WARP_W (2 * SA_BUF_W)            // 2304
#define SA_WORDS  (8 * SA_WARP_W)           // 18432
#define SRED_WRP  (32 * 34)                 // 1088 (overlaid on sA)
#define REC_SMEM_BYTES ((SW_WORDS + SA_WORDS + 256) * 4)

__device__ __forceinline__ void stage_chunk(const uint32_t* __restrict__ hsrc, int kbase,
                                            uint32_t sdst_bytes, int lane) {
#pragma unroll
    for (int j = 0; j < 8; j++) {
        int id = j * 32 + lane;
        int srow = id >> 3;            // 0..31
        int s16 = id & 7;              // 16B column within 32-word chunk
        cp16(sdst_bytes + (uint32_t)(srow * SA_STRIDE + s16 * 4) * 4,
             hsrc + (size_t)srow * H_ + kbase + s16 * 4);
    }
    asm volatile("cp.async.commit_group;" ::: "memory");
}

__launch_bounds__(256, 1)
__global__ void recurrence_kernel(const float* __restrict__ c0, float* __restrict__ d_out) {
    extern __shared__ uint32_t smem[];
    float* sred = reinterpret_cast<float*>(smem + SW_WORDS);           // overlay on sA
    float* sc = reinterpret_cast<float*>(smem + SW_WORDS + SA_WORDS);  // [256]

    const int tid = threadIdx.x;
    const int cta = blockIdx.x;
    const int lane = tid & 31, warp = tid >> 5;
    const uint32_t smem_b = (uint32_t)__cvta_generic_to_shared(smem);
    const int b = tid >> 3, u = tid & 7;

    // --- init: copy pre-converted W_hh slice into sW ---
#pragma unroll
    for (int it = 0; it < 32; it++) {
        int lin = tid + it * 256;      // float4 id 0..8191
        int r = lin >> 8;              // smem row 0..31 (g*8+u)
        int c4 = lin & 255;
        int gg = r >> 3, rr = r & 7;
        cp16(smem_b + (uint32_t)(r * SW_STRIDE + c4 * 4) * 4,
             g_whh_tf + (size_t)(gg * H_ + cta * 8 + rr) * H_ + c4 * 4);
    }
    asm volatile("cp.async.commit_group;" ::: "memory");
    sc[tid] = c0[(size_t)b * H_ + cta * 8 + u];
    asm volatile("cp.async.wait_group 0;" ::: "memory");
    __syncthreads();

    const int kw0 = warp * 128;
    const uint32_t sa_bytes = smem_b + (uint32_t)(SW_WORDS + warp * SA_WARP_W) * 4;
    unsigned* my_cnt = &g_gcnt[cta >> 4];
    const unsigned* wait_cnt = &g_gcnt[warp];

    for (int t = 0; t < T_; t++) {
        const uint32_t* hsrc = g_hstf + (size_t)t * B_ * H_;   // h[t-1]

        // prefetch xproj (consumed in epilogue)
        const size_t xb = (size_t)(t * B_ + b) * G_ + (size_t)cta * 8 + u;
        float xp0 = g_xproj[xb];
        float xp1 = g_xproj[xb + H_];
        float xp2 = g_xproj[xb + 2 * H_];
        float xp3 = g_xproj[xb + 3 * H_];

        float acc[2][4][4];
#pragma unroll
        for (int i = 0; i < 2; i++)
#pragma unroll
            for (int j = 0; j < 4; j++)
#pragma unroll
                for (int r = 0; r < 4; r++) acc[i][j][r] = 0.f;

        // wait for the 16 producer CTAs of this warp's k-range
        if (t > 0) {
            if (lane == 0) {
                unsigned need = 16u * (unsigned)t;
                while (ld_acq(wait_cnt) < need) {}
            }
            __syncwarp();
        }

        stage_chunk(hsrc, kw0, sa_bytes, lane);

#pragma unroll
        for (int cc = 0; cc < 4; cc++) {
            if (cc < 3) {
                stage_chunk(hsrc, kw0 + (cc + 1) * 32,
                            sa_bytes + (uint32_t)(((cc + 1) & 1) * SA_BUF_W) * 4, lane);
                asm volatile("cp.async.wait_group 1;" ::: "memory");
            } else {
                asm volatile("cp.async.wait_group 0;" ::: "memory");
            }
            __syncwarp();

            const uint32_t abase = sa_bytes + (uint32_t)((cc & 1) * SA_BUF_W) * 4;
            const int colc = kw0 + cc * 32;
            const int arow = ((lane >> 3) & 1) * 8 + (lane & 7);
            const int ahi = (lane >> 4) * 4;

#pragma unroll
            for (int kp = 0; kp < 2; kp++) {
                uint32_t bfr[4][4];
#pragma unroll
                for (int j = 0; j < 4; j++) {
                    int n = j * 8 + (lane & 7);
                    int col = colc + kp * 16 + (lane >> 3) * 4;
                    ldsm4(bfr[j][0], bfr[j][1], bfr[j][2], bfr[j][3],
                          smem_b + (uint32_t)(n * SW_STRIDE + col) * 4);
                }
#pragma unroll
                for (int k2 = 0; k2 < 2; k2++) {
                    int kt = kp * 2 + k2;
                    uint32_t afr[2][4];
#pragma unroll
                    for (int i = 0; i < 2; i++) {
                        int row = i * 16 + arow;
                        ldsm4(afr[i][0], afr[i][1], afr[i][2], afr[i][3],
                              abase + (uint32_t)(row * SA_STRIDE + kt * 8 + ahi) * 4);
                    }
#pragma unroll
                    for (int i = 0; i < 2; i++)
#pragma unroll
                        for (int j = 0; j < 4; j++)
                            mma_tf32(acc[i][j][0], acc[i][j][1], acc[i][j][2], acc[i][j][3],
                                     afr[i][0], afr[i][1], afr[i][2], afr[i][3],
                                     bfr[j][k2 * 2], bfr[j][k2 * 2 + 1]);
                }
            }
        }

        __syncthreads();   // all warps done with sA -> safe to overlay sred

        const int grp = lane >> 2, tig = lane & 3;
#pragma unroll
        for (int i = 0; i < 2; i++) {
#pragma unroll
            for (int j = 0; j < 4; j++) {
                int m0 = i * 16 + grp, n0 = j * 8 + tig * 2;
                float* p = sred + warp * SRED_WRP;
                *reinterpret_cast<float2*>(p + m0 * 34 + n0) =
                    make_float2(acc[i][j][0], acc[i][j][1]);
                *reinterpret_cast<float2*>(p + (m0 + 8) * 34 + n0) =
                    make_float2(acc[i][j][2], acc[i][j][3]);
            }
        }
        __syncthreads();

        // reduce 8 partials + xproj, LSTM cell
        float s0 = xp0, s1 = xp1, s2 = xp2, s3 = xp3;
#pragma unroll
        for (int w = 0; w < 8; w++) {
            const float* p = sred + w * SRED_WRP + b * 34 + u;
            s0 += p[0]; s1 += p[8]; s2 += p[16]; s3 += p[24];
        }
        float iv = 1.f / (1.f + expf(-s0));
        float fv = 1.f / (1.f + expf(-s1));
        float gv = tanhf(s2);
        float ov = 1.f / (1.f + expf(-s3));
        float c = fv * sc[tid] + iv * gv;
        sc[tid] = c;
        float h = ov * tanhf(c);

        g_hstf[(size_t)(t + 1) * B_ * H_ + (size_t)b * H_ + cta * 8 + u] = f2tf(h);
        if (t == T_ - 1) {
            size_t off_h = (size_t)BT * (N0 + N1);
            d_out[off_h + (size_t)b * H_ + cta * 8 + u] = h;
            d_out[off_h + (size_t)B_ * H_ + (size_t)b * H_ + cta * 8 + u] = c;
        }

        __syncthreads();   // h writes done CTA-wide; also guards sA reuse next iter
        if (t < T_ - 1 && tid == 0) red_release(my_cnt, 1u);
    }
}

// ------------------------- launch ----------------------------------------
extern "C" void kernel_launch(void* const* d_in, const int* in_sizes, int n_in,
                              void* d_out, int out_size) {
    const int*   tok0 = (const int*)d_in[0];
    const int*   tok1 = (const int*)d_in[1];
    const float* h0   = (const float*)d_in[2];
    const float* c0   = (const float*)d_in[3];
    const float* emb0 = (const float*)d_in[4];
    const float* emb1 = (const float*)d_in[5];
    const float* W_ih = (const float*)d_in[6];
    const float* W_hh = (const float*)d_in[7];
    const float* b_ih = (const float*)d_in[8];
    const float* b_hh = (const float*)d_in[9];
    const float* Wd0  = (const float*)d_in[10];
    const float* bd0  = (const float*)d_in[11];
    const float* Wd1  = (const float*)d_in[12];
    const float* bd1  = (const float*)d_in[13];
    float* out = (float*)d_out;

    const int GEMM_SMEM = (2 * 128 * 36 + 2 * 64 * 36) * 4;   // 55296

    cudaFuncSetAttribute(gemm_tf32_kernel<false>, cudaFuncAttributeMaxDynamicSharedMemorySize, GEMM_SMEM);
    cudaFuncSetAttribute(gemm_tf32_kernel<true>,  cudaFuncAttributeMaxDynamicSharedMemorySize, GEMM_SMEM);
    cudaFuncSetAttribute(recurrence_kernel, cudaFuncAttributeMaxDynamicSharedMemorySize, REC_SMEM_BYTES);

    void *px, *pxp, *phs, *pwih, *pwd0, *pwd1;
    cudaGetSymbolAddress(&px, g_x);
    cudaGetSymbolAddress(&pxp, g_xproj);
    cudaGetSymbolAddress(&phs, g_hstf);
    cudaGetSymbolAddress(&pwih, g_wih_tf);
    cudaGetSymbolAddress(&pwd0, g_wd0_tf);
    cudaGetSymbolAddress(&pwd1, g_wd1_tf);

    prep_kernel<<<2048, 256>>>(W_ih, W_hh, Wd0, Wd1, h0);
    pack_kernel<<<BT, 128>>>(tok0, tok1, emb0, emb1);

    // xproj = x @ W_ih^T + (b_ih + b_hh)
    gemm_tf32_kernel<false><<<dim3(G_ / 64, BT / 128), 256, GEMM_SMEM>>>(
        (const uint32_t*)px, (const uint32_t*)pwih, b_ih, b_hh, (float*)pxp, BT, G_, E2);

    recurrence_kernel<<<NCTA, 256, REC_SMEM_BYTES>>>(c0, out);

    const uint32_t* hsA = (const uint32_t*)phs + (size_t)B_ * H_;  // skip h0 rows

    // dec0 = hs @ Wd0^T + bd0   (rows remapped t*B+b -> b*T+t)
    gemm_tf32_kernel<true><<<dim3(N0 / 64, BT / 128), 256, GEMM_SMEM>>>(
        hsA, (const uint32_t*)pwd0, bd0, nullptr, out, BT, N0, H_);

    // dec1 = hs @ Wd1^T + bd1
    gemm_tf32_kernel<true><<<dim3(N1 / 64, BT / 128), 256, GEMM_SMEM>>>(
        hsA, (const uint32_t*)pwd1, bd1, nullptr, out + (size_t)BT * N0, BT, N1, H_);
}

// round 5
// speedup vs baseline: 1.3980x; 1.0492x over previous
#include <cuda_runtime.h>
#include <cstdint>

#define B_   32
#define T_   512
#define E2   512
#define H_   1024
#define G_   4096
#define BT   16384
#define N0   2048
#define N1   512
#define NCTA 128

// ------------------------- scratch (device globals, no allocs) -----------
__device__ uint32_t g_x[(size_t)BT * E2];          // embeddings, tf32 bits
__device__ float    g_xproj[(size_t)BT * G_];      // x @ W_ih^T + b (fp32)
__device__ uint32_t g_hstf[(size_t)(BT + B_) * H_];// tf32 h: rows 0..31 = h0, row (t+1)*32+b = h[t]
__device__ uint32_t g_wih_tf[(size_t)G_ * E2];
__device__ uint32_t g_whh_tf[(size_t)G_ * H_];
__device__ uint32_t g_wd0_tf[(size_t)N0 * H_];
__device__ uint32_t g_wd1_tf[(size_t)N1 * H_];
__device__ unsigned g_gcnt[8];                     // per-group step counters

// ------------------------- helpers ---------------------------------------
__device__ __forceinline__ uint32_t f2tf(float f) {
    uint32_t u;
    asm("cvt.rna.tf32.f32 %0, %1;" : "=r"(u) : "f"(f));
    return u;
}

__device__ __forceinline__ void mma_tf32(float& c0, float& c1, float& c2, float& c3,
                                         uint32_t a0, uint32_t a1, uint32_t a2, uint32_t a3,
                                         uint32_t b0, uint32_t b1) {
    asm volatile(
        "mma.sync.aligned.m16n8k8.row.col.f32.tf32.tf32.f32 "
        "{%0,%1,%2,%3},{%4,%5,%6,%7},{%8,%9},{%0,%1,%2,%3};"
        : "+f"(c0), "+f"(c1), "+f"(c2), "+f"(c3)
        : "r"(a0), "r"(a1), "r"(a2), "r"(a3), "r"(b0), "r"(b1));
}

__device__ __forceinline__ void ldsm4(uint32_t& r0, uint32_t& r1, uint32_t& r2, uint32_t& r3,
                                      uint32_t saddr) {
    asm volatile("ldmatrix.sync.aligned.m8n8.x4.shared.b16 {%0,%1,%2,%3}, [%4];"
                 : "=r"(r0), "=r"(r1), "=r"(r2), "=r"(r3) : "r"(saddr));
}

__device__ __forceinline__ void cp16(uint32_t sdst, const void* gsrc) {
    asm volatile("cp.async.cg.shared.global [%0], [%1], 16;" :: "r"(sdst), "l"(gsrc) : "memory");
}

__device__ __forceinline__ unsigned ld_acq(const unsigned* p) {
    unsigned v;
    asm volatile("ld.acquire.gpu.u32 %0, [%1];" : "=r"(v) : "l"(p));
    return v;
}

__device__ __forceinline__ void red_release(unsigned* p, unsigned v) {
    asm volatile("red.release.gpu.global.add.u32 [%0], %1;" :: "l"(p), "r"(v) : "memory");
}

// ------------------------- prep: convert weights / h0, reset counters ----
__global__ void prep_kernel(const float* __restrict__ W_ih, const float* __restrict__ W_hh,
                            const float* __restrict__ Wd0, const float* __restrict__ Wd1,
                            const float* __restrict__ h0) {
    size_t i = (size_t)blockIdx.x * blockDim.x + threadIdx.x;
    size_t stride = (size_t)gridDim.x * blockDim.x;
    for (size_t k = i; k < (size_t)G_ * H_; k += stride) g_whh_tf[k] = f2tf(W_hh[k]);
    for (size_t k = i; k < (size_t)G_ * E2; k += stride) g_wih_tf[k] = f2tf(W_ih[k]);
    for (size_t k = i; k < (size_t)N0 * H_; k += stride) g_wd0_tf[k] = f2tf(Wd0[k]);
    for (size_t k = i; k < (size_t)N1 * H_; k += stride) g_wd1_tf[k] = f2tf(Wd1[k]);
    if (i < (size_t)B_ * H_) g_hstf[i] = f2tf(h0[i]);   // rows 0..31 = h[-1]
    if (i < 8) g_gcnt[i] = 0;
}

// ------------------------- pack: gather embeddings as tf32 ---------------
__global__ void pack_kernel(const int* __restrict__ tok0, const int* __restrict__ tok1,
                            const float* __restrict__ emb0, const float* __restrict__ emb1) {
    int row = blockIdx.x;           // row = t*32 + b
    int t = row >> 5, b = row & 31;
    int tid = threadIdx.x;          // 128 threads, 512 words per row
    uint4* dst = reinterpret_cast<uint4*>(g_x + (size_t)row * E2);
    float4 v;
    if (tid < 64) {
        int tk = tok0[b * T_ + t];
        v = reinterpret_cast<const float4*>(emb0 + (size_t)tk * 256)[tid];
    } else {
        int tk = tok1[b * T_ + t];
        v = reinterpret_cast<const float4*>(emb1 + (size_t)tk * 256)[tid - 64];
    }
    dst[tid] = make_uint4(f2tf(v.x), f2tf(v.y), f2tf(v.z), f2tf(v.w));
}

// ------------------------- tf32 GEMM v2 (ldmatrix fragments) -------------
// C[M,N] = A[M,K] @ Bm[N,K]^T + bias1 + bias2.  BM=128, BN=64, BK=32, 256 thr.
// A, Bm hold tf32 bit patterns. REMAP: out row (m%32)*512 + m/32.
template <bool REMAP>
__launch_bounds__(256, 2)
__global__ void gemm_tf32_kernel(const uint32_t* __restrict__ A, const uint32_t* __restrict__ Bm,
                                 const float* __restrict__ bias1, const float* __restrict__ bias2,
                                 float* __restrict__ C, int M, int N, int K) {
    extern __shared__ uint32_t smem[];
    uint32_t* sA = smem;                 // [2][128][36]
    uint32_t* sB = smem + 2 * 128 * 36;  // [2][64][36]

    const int tid = threadIdx.x;
    const int bn = blockIdx.x * 64;
    const int bm = blockIdx.y * 128;
    const int lane = tid & 31, warp = tid >> 5;
    const int wm = (warp >> 1) * 32;
    const int wn = (warp & 1) * 32;
    const int grp = lane >> 2, tig = lane & 3;
    const int KT = K >> 5;
    const uint32_t smem_b = (uint32_t)__cvta_generic_to_shared(smem);

    uint4 ra[4], rb[2];

    auto gload = [&](int kb) {
#pragma unroll
        for (int i = 0; i < 4; i++) {
            int lin = tid + i * 256;
            int r = lin >> 3, c4 = lin & 7;
            ra[i] = reinterpret_cast<const uint4*>(A + (size_t)(bm + r) * K + kb * 32)[c4];
        }
#pragma unroll
        for (int i = 0; i < 2; i++) {
            int lin = tid + i * 256;
            int r = lin >> 3, c4 = lin & 7;
            rb[i] = reinterpret_cast<const uint4*>(Bm + (size_t)(bn + r) * K + kb * 32)[c4];
        }
    };
    auto sstore = [&](int buf) {
        uint32_t* a = sA + buf * 128 * 36;
        uint32_t* b = sB + buf * 64 * 36;
#pragma unroll
        for (int i = 0; i < 4; i++) {
            int lin = tid + i * 256;
            int r = lin >> 3, c4 = lin & 7;
            *reinterpret_cast<uint4*>(a + r * 36 + c4 * 4) = ra[i];
        }
#pragma unroll
        for (int i = 0; i < 2; i++) {
            int lin = tid + i * 256;
            int r = lin >> 3, c4 = lin & 7;
            *reinterpret_cast<uint4*>(b + r * 36 + c4 * 4) = rb[i];
        }
    };

    float acc[2][4][4];
#pragma unroll
    for (int i = 0; i < 2; i++)
#pragma unroll
        for (int j = 0; j < 4; j++)
#pragma unroll
            for (int r = 0; r < 4; r++) acc[i][j][r] = 0.f;

    gload(0);
    sstore(0);
    __syncthreads();

    const int arow = ((lane >> 3) & 1) * 8 + (lane & 7);
    const int ahi = (lane >> 4) * 4;

    for (int kb = 0; kb < KT; kb++) {
        if (kb + 1 < KT) gload(kb + 1);
        const uint32_t aoff = (uint32_t)((kb & 1) * 128 * 36) * 4;
        const uint32_t boff = (uint32_t)(2 * 128 * 36 + (kb & 1) * 64 * 36) * 4;

#pragma unroll
        for (int kp = 0; kp < 2; kp++) {
            uint32_t bfr[4][4];
#pragma unroll
            for (int j = 0; j < 4; j++) {
                int n = wn + j * 8 + (lane & 7);
                int col = kp * 16 + (lane >> 3) * 4;
                ldsm4(bfr[j][0], bfr[j][1], bfr[j][2], bfr[j][3],
                      smem_b + boff + (uint32_t)(n * 36 + col) * 4);
            }
#pragma unroll
            for (int k2 = 0; k2 < 2; k2++) {
                int kt = kp * 2 + k2;
                uint32_t afr[2][4];
#pragma unroll
                for (int i = 0; i < 2; i++) {
                    int row = wm + i * 16 + arow;
                    ldsm4(afr[i][0], afr[i][1], afr[i][2], afr[i][3],
                          smem_b + aoff + (uint32_t)(row * 36 + kt * 8 + ahi) * 4);
                }
#pragma unroll
                for (int i = 0; i < 2; i++)
#pragma unroll
                    for (int j = 0; j < 4; j++)
                        mma_tf32(acc[i][j][0], acc[i][j][1], acc[i][j][2], acc[i][j][3],
                                 afr[i][0], afr[i][1], afr[i][2], afr[i][3],
                                 bfr[j][k2 * 2], bfr[j][k2 * 2 + 1]);
            }
        }
        if (kb + 1 < KT) {
            __syncthreads();
            sstore((kb + 1) & 1);
            __syncthreads();
        }
    }

#pragma unroll
    for (int i = 0; i < 2; i++) {
#pragma unroll
        for (int j = 0; j < 4; j++) {
            int col = bn + wn + j * 8 + tig * 2;
            float bv0 = 0.f, bv1 = 0.f;
            if (bias1) { bv0 = bias1[col]; bv1 = bias1[col + 1]; }
            if (bias2) { bv0 += bias2[col]; bv1 += bias2[col + 1]; }
            int r0 = bm + wm + i * 16 + grp;
            int r1 = r0 + 8;
            int or0 = REMAP ? ((r0 & 31) * T_ + (r0 >> 5)) : r0;
            int or1 = REMAP ? ((r1 & 31) * T_ + (r1 >> 5)) : r1;
            float2 v0 = make_float2(acc[i][j][0] + bv0, acc[i][j][1] + bv1);
            float2 v1 = make_float2(acc[i][j][2] + bv0, acc[i][j][3] + bv1);
            *reinterpret_cast<float2*>(C + (size_t)or0 * N + col) = v0;
            *reinterpret_cast<float2*>(C + (size_t)or1 * N + col) = v1;
        }
    }
}

// ------------------------- persistent LSTM recurrence v4b -----------------
// 128 CTAs x 256 thr (8 warps). CTA owns 8 hidden units -> 32 gate rows.
// Warp w handles k in [128w,128w+128) -> needs h units from CTAs 16w..16w+15
// only. Fine-grained sync via 8 group counters (red.release / ld.acquire).
// Partial sums overlay each warp's OWN staging region -> only 2 BARs/step.
// SRED_STR must be EVEN (float2 stores need 8-byte alignment).
#define SW_STRIDE 1028
#define SW_WORDS  (32 * SW_STRIDE)          // 32896
#define SA_STRIDE 36
#define SA_BUF_W  (32 * SA_STRIDE)          // 1152
#define SA_WARP_W (2 * SA_BUF_W)            // 2304
#define SA_WORDS  (8 * SA_WARP_W)           // 18432
#define SRED_STR  34
#define SRED_WRP  (32 * SRED_STR)           // 1088 <= SA_WARP_W (warp-private overlay)
#define REC_SMEM_BYTES ((SW_WORDS + SA_WORDS + 256) * 4)

__device__ __forceinline__ void stage_chunk(const uint32_t* __restrict__ hsrc, int kbase,
                                            uint32_t sdst_bytes, int lane) {
#pragma unroll
    for (int j = 0; j < 8; j++) {
        int id = j * 32 + lane;
        int srow = id >> 3;            // 0..31
        int s16 = id & 7;              // 16B column within 32-word chunk
        cp16(sdst_bytes + (uint32_t)(srow * SA_STRIDE + s16 * 4) * 4,
             hsrc + (size_t)srow * H_ + kbase + s16 * 4);
    }
    asm volatile("cp.async.commit_group;" ::: "memory");
}

__launch_bounds__(256, 1)
__global__ void recurrence_kernel(const float* __restrict__ c0, float* __restrict__ d_out) {
    extern __shared__ uint32_t smem[];
    float* sred = reinterpret_cast<float*>(smem + SW_WORDS);           // overlay on sA
    float* sc = reinterpret_cast<float*>(smem + SW_WORDS + SA_WORDS);  // [256]

    const int tid = threadIdx.x;
    const int cta = blockIdx.x;
    const int lane = tid & 31, warp = tid >> 5;
    const uint32_t smem_b = (uint32_t)__cvta_generic_to_shared(smem);
    const int b = tid >> 3, u = tid & 7;

    // --- init: copy pre-converted W_hh slice into sW ---
#pragma unroll
    for (int it = 0; it < 32; it++) {
        int lin = tid + it * 256;      // float4 id 0..8191
        int r = lin >> 8;              // smem row 0..31 (g*8+u)
        int c4 = lin & 255;
        int gg = r >> 3, rr = r & 7;
        cp16(smem_b + (uint32_t)(r * SW_STRIDE + c4 * 4) * 4,
             g_whh_tf + (size_t)(gg * H_ + cta * 8 + rr) * H_ + c4 * 4);
    }
    asm volatile("cp.async.commit_group;" ::: "memory");
    sc[tid] = c0[(size_t)b * H_ + cta * 8 + u];
    asm volatile("cp.async.wait_group 0;" ::: "memory");
    __syncthreads();

    const int kw0 = warp * 128;
    const uint32_t sa_bytes = smem_b + (uint32_t)(SW_WORDS + warp * SA_WARP_W) * 4;
    unsigned* my_cnt = &g_gcnt[cta >> 4];
    const unsigned* wait_cnt = &g_gcnt[warp];

    for (int t = 0; t < T_; t++) {
        const uint32_t* hsrc = g_hstf + (size_t)t * B_ * H_;   // h[t-1]

        // prefetch xproj (consumed in epilogue)
        const size_t xb = (size_t)(t * B_ + b) * G_ + (size_t)cta * 8 + u;
        float xp0 = g_xproj[xb];
        float xp1 = g_xproj[xb + H_];
        float xp2 = g_xproj[xb + 2 * H_];
        float xp3 = g_xproj[xb + 3 * H_];

        float acc[2][4][4];
#pragma unroll
        for (int i = 0; i < 2; i++)
#pragma unroll
            for (int j = 0; j < 4; j++)
#pragma unroll
                for (int r = 0; r < 4; r++) acc[i][j][r] = 0.f;

        // wait for the 16 producer CTAs of this warp's k-range
        if (t > 0) {
            if (lane == 0) {
                unsigned need = 16u * (unsigned)t;
                while (ld_acq(wait_cnt) < need) {}
            }
            __syncwarp();
        }

        stage_chunk(hsrc, kw0, sa_bytes, lane);

#pragma unroll
        for (int cc = 0; cc < 4; cc++) {
            if (cc < 3) {
                stage_chunk(hsrc, kw0 + (cc + 1) * 32,
                            sa_bytes + (uint32_t)(((cc + 1) & 1) * SA_BUF_W) * 4, lane);
                asm volatile("cp.async.wait_group 1;" ::: "memory");
            } else {
                asm volatile("cp.async.wait_group 0;" ::: "memory");
            }
            __syncwarp();

            const uint32_t abase = sa_bytes + (uint32_t)((cc & 1) * SA_BUF_W) * 4;
            const int colc = cc * 32;
            const int arow = ((lane >> 3) & 1) * 8 + (lane & 7);
            const int ahi = (lane >> 4) * 4;

#pragma unroll
            for (int kp = 0; kp < 2; kp++) {
                uint32_t bfr[4][4];
#pragma unroll
                for (int j = 0; j < 4; j++) {
                    int n = j * 8 + (lane & 7);
                    int col = kw0 + colc + kp * 16 + (lane >> 3) * 4;
                    ldsm4(bfr[j][0], bfr[j][1], bfr[j][2], bfr[j][3],
                          smem_b + (uint32_t)(n * SW_STRIDE + col) * 4);
                }
#pragma unroll
                for (int k2 = 0; k2 < 2; k2++) {
                    int kt = kp * 2 + k2;
                    uint32_t afr[2][4];
#pragma unroll
                    for (int i = 0; i < 2; i++) {
                        int row = i * 16 + arow;
                        ldsm4(afr[i][0], afr[i][1], afr[i][2], afr[i][3],
                              abase + (uint32_t)(row * SA_STRIDE + kt * 8 + ahi) * 4);
                    }
#pragma unroll
                    for (int i = 0; i < 2; i++)
#pragma unroll
                        for (int j = 0; j < 4; j++)
                            mma_tf32(acc[i][j][0], acc[i][j][1], acc[i][j][2], acc[i][j][3],
                                     afr[i][0], afr[i][1], afr[i][2], afr[i][3],
                                     bfr[j][k2 * 2], bfr[j][k2 * 2 + 1]);
                }
            }
        }

        // write k-partials into THIS warp's own staging region (warp-private:
        // my ldsm reads of this region are already complete via reg deps)
        __syncwarp();
        const int grp = lane >> 2, tig = lane & 3;
        {
            float* p = sred + warp * SA_WARP_W;   // overlay base of own sA
#pragma unroll
            for (int i = 0; i < 2; i++) {
#pragma unroll
                for (int j = 0; j < 4; j++) {
                    int m0 = i * 16 + grp, n0 = j * 8 + tig * 2;
                    *reinterpret_cast<float2*>(p + m0 * SRED_STR + n0) =
                        make_float2(acc[i][j][0], acc[i][j][1]);
                    *reinterpret_cast<float2*>(p + (m0 + 8) * SRED_STR + n0) =
                        make_float2(acc[i][j][2], acc[i][j][3]);
                }
            }
        }
        __syncthreads();   // partials visible to all warps

        // reduce 8 partials + xproj, LSTM cell
        float s0 = xp0, s1 = xp1, s2 = xp2, s3 = xp3;
#pragma unroll
        for (int w = 0; w < 8; w++) {
            const float* p = sred + w * SA_WARP_W + b * SRED_STR + u;
            s0 += p[0]; s1 += p[8]; s2 += p[16]; s3 += p[24];
        }
        float iv = 1.f / (1.f + expf(-s0));
        float fv = 1.f / (1.f + expf(-s1));
        float gv = tanhf(s2);
        float ov = 1.f / (1.f + expf(-s3));
        float c = fv * sc[tid] + iv * gv;
        sc[tid] = c;
        float h = ov * tanhf(c);

        g_hstf[(size_t)(t + 1) * B_ * H_ + (size_t)b * H_ + cta * 8 + u] = f2tf(h);
        if (t == T_ - 1) {
            size_t off_h = (size_t)BT * (N0 + N1);
            d_out[off_h + (size_t)b * H_ + cta * 8 + u] = h;
            d_out[off_h + (size_t)B_ * H_ + (size_t)b * H_ + cta * 8 + u] = c;
        }

        __syncthreads();   // h writes done CTA-wide; guards sred/sA reuse next iter
        if (t < T_ - 1 && tid == 0) red_release(my_cnt, 1u);
    }
}

// ------------------------- launch ----------------------------------------
extern "C" void kernel_launch(void* const* d_in, const int* in_sizes, int n_in,
                              void* d_out, int out_size) {
    const int*   tok0 = (const int*)d_in[0];
    const int*   tok1 = (const int*)d_in[1];
    const float* h0   = (const float*)d_in[2];
    const float* c0   = (const float*)d_in[3];
    const float* emb0 = (const float*)d_in[4];
    const float* emb1 = (const float*)d_in[5];
    const float* W_ih = (const float*)d_in[6];
    const float* W_hh = (const float*)d_in[7];
    const float* b_ih = (const float*)d_in[8];
    const float* b_hh = (const float*)d_in[9];
    const float* Wd0  = (const float*)d_in[10];
    const float* bd0  = (const float*)d_in[11];
    const float* Wd1  = (const float*)d_in[12];
    const float* bd1  = (const float*)d_in[13];
    float* out = (float*)d_out;

    const int GEMM_SMEM = (2 * 128 * 36 + 2 * 64 * 36) * 4;   // 55296

    cudaFuncSetAttribute(gemm_tf32_kernel<false>, cudaFuncAttributeMaxDynamicSharedMemorySize, GEMM_SMEM);
    cudaFuncSetAttribute(gemm_tf32_kernel<true>,  cudaFuncAttributeMaxDynamicSharedMemorySize, GEMM_SMEM);
    cudaFuncSetAttribute(recurrence_kernel, cudaFuncAttributeMaxDynamicSharedMemorySize, REC_SMEM_BYTES);

    void *px, *pxp, *phs, *pwih, *pwd0, *pwd1;
    cudaGetSymbolAddress(&px, g_x);
    cudaGetSymbolAddress(&pxp, g_xproj);
    cudaGetSymbolAddress(&phs, g_hstf);
    cudaGetSymbolAddress(&pwih, g_wih_tf);
    cudaGetSymbolAddress(&pwd0, g_wd0_tf);
    cudaGetSymbolAddress(&pwd1, g_wd1_tf);

    prep_kernel<<<2048, 256>>>(W_ih, W_hh, Wd0, Wd1, h0);
    pack_kernel<<<BT, 128>>>(tok0, tok1, emb0, emb1);

    // xproj = x @ W_ih^T + (b_ih + b_hh)
    gemm_tf32_kernel<false><<<dim3(G_ / 64, BT / 128), 256, GEMM_SMEM>>>(
        (const uint32_t*)px, (const uint32_t*)pwih, b_ih, b_hh, (float*)pxp, BT, G_, E2);

    recurrence_kernel<<<NCTA, 256, REC_SMEM_BYTES>>>(c0, out);

    const uint32_t* hsA = (const uint32_t*)phs + (size_t)B_ * H_;  // skip h0 rows

    // dec0 = hs @ Wd0^T + bd0   (rows remapped t*B+b -> b*T+t)
    gemm_tf32_kernel<true><<<dim3(N0 / 64, BT / 128), 256, GEMM_SMEM>>>(
        hsA, (const uint32_t*)pwd0, bd0, nullptr, out, BT, N0, H_);

    // dec1 = hs @ Wd1^T + bd1
    gemm_tf32_kernel<true><<<dim3(N1 / 64, BT / 128), 256, GEMM_SMEM>>>(
        hsA, (const uint32_t*)pwd1, bd1, nullptr, out + (size_t)BT * N0, BT, N1, H_);
}